// round 15
// baseline (speedup 1.0000x reference)
#include <cuda_runtime.h>
#include <cuda_fp16.h>
#include <math.h>
#include <stdint.h>

#define Bb 8
#define CC 512
#define GG 32
#define CGc 16
#define NTOK 4096
#define EPSV 1e-5f

// ---------------- scratch (device globals; no runtime allocation) ----------------
__device__ __half g_h  [(size_t)Bb*NTOK*CC];          // GN output, fp16
__device__ __half g_qkv[(size_t)Bb*NTOK*3*CC];        // packed q|k|v, fp16
__device__ __half g_vth[(size_t)Bb*NTOK*CC];          // V^T per batch fp16 [CC][NTOK]
__device__ __half g_ao [(size_t)Bb*NTOK*CC];          // attention output fp16
__device__ __half g_s  [(size_t)Bb*NTOK*NTOK];        // fp16 raw scores (256 MB)
__device__ __half g_p  [(size_t)Bb*NTOK*NTOK];        // fp16 probabilities (256 MB)
__device__ __half g_w16[4*(size_t)CC*CC];             // wqkvT (3 sections) + woT, fp16
__device__ float  g_bqkv[3*CC];                       // packed biases

// ---------------- GroupNorm -> fp16 ----------------
__global__ void gn_kernel(const float* __restrict__ x,
                          const float* __restrict__ sc,
                          const float* __restrict__ bi,
                          __half* __restrict__ h) {
    int b = blockIdx.x / GG, g = blockIdx.x % GG;
    const float* xp = x + (size_t)b*NTOK*CC + g*CGc;
    __half*      hp = h + (size_t)b*NTOK*CC + g*CGc;
    int tid = threadIdx.x;

    float s = 0.f, ss = 0.f;
    for (int i = tid; i < NTOK*CGc; i += 256) {
        int n = i >> 4, c = i & 15;
        float v = xp[(size_t)n*CC + c];
        s += v; ss += v*v;
    }
    __shared__ float r1[256], r2[256];
    r1[tid] = s; r2[tid] = ss; __syncthreads();
    for (int o = 128; o > 0; o >>= 1) {
        if (tid < o) { r1[tid] += r1[tid+o]; r2[tid] += r2[tid+o]; }
        __syncthreads();
    }
    const float invn = 1.f / (float)(NTOK*CGc);
    float mean = r1[0] * invn;
    float var  = r2[0] * invn - mean*mean;
    float inv  = rsqrtf(var + EPSV);

    for (int i = tid; i < NTOK*CGc; i += 256) {
        int n = i >> 4, c = i & 15;
        float v = xp[(size_t)n*CC + c];
        hp[(size_t)n*CC + c] =
            __float2half((v - mean) * inv * sc[g*CGc + c] + bi[g*CGc + c]);
    }
}

// ---------------- transpose fp32 -> fp16: in[R][Cc] -> out[Cc][R] ----------------
__global__ void transpose_f2h(const float* __restrict__ in, __half* __restrict__ out,
                              int R, int Cc) {
    __shared__ float t[32][33];
    int r0 = blockIdx.x * 32, c0 = blockIdx.y * 32;
    int x = threadIdx.x, y = threadIdx.y;
    #pragma unroll
    for (int i = 0; i < 32; i += 8)
        t[y+i][x] = in[(size_t)(r0+y+i)*Cc + c0 + x];
    __syncthreads();
    #pragma unroll
    for (int i = 0; i < 32; i += 8)
        out[(size_t)(c0+y+i)*R + r0 + x] = __float2half(t[x][y+i]);
}

// ---------------- batched transpose fp16: in[R][ldi] -> out[Cc][R] ----------------
__global__ void transpose_h2h(const __half* __restrict__ in, __half* __restrict__ out,
                              int R, int Cc, int ldi,
                              long long sIn, long long sOut) {
    __shared__ __half t[32][34];
    int b = blockIdx.z;
    int r0 = blockIdx.x * 32, c0 = blockIdx.y * 32;
    const __half* ip = in  + (size_t)b*sIn;
    __half*       op = out + (size_t)b*sOut;
    int x = threadIdx.x, y = threadIdx.y;
    #pragma unroll
    for (int i = 0; i < 32; i += 8)
        t[y+i][x] = ip[(size_t)(r0+y+i)*ldi + c0 + x];
    __syncthreads();
    #pragma unroll
    for (int i = 0; i < 32; i += 8)
        op[(size_t)(c0+y+i)*R + r0 + x] = t[x][y+i];
}

// ---------------- bias pack ----------------
__global__ void pack_bias(const float* __restrict__ bq, const float* __restrict__ bk,
                          const float* __restrict__ bv, float* __restrict__ o) {
    int i = threadIdx.x + blockIdx.x * 256;
    if (i < CC)            o[i] = bq[i];
    else if (i < 2*CC)     o[i] = bk[i - CC];
    else if (i < 3*CC)     o[i] = bv[i - 2*CC];
}

// ---------------- fp16 tensor-core GEMM (m16n8k16), 3-stage cp.async ring ----------------
// C[M,N] = alpha * A[M,K] @ Bt^T (+bias)(+resid); A [M][K] fp16 (lda), Bt [N][K]
// fp16 (ldbt). HOUT: C fp16, else fp32. resid only in fp32 path.
#define HST 40
#define HTSZ (128*HST)                 /* halves per tile buffer (10240 B) */
#define NSTG 3
#define HSMEM (2*NSTG*HTSZ*2)          /* 61440 B dynamic smem */

template<bool HOUT>
__global__ __launch_bounds__(256)
void hgemm(const __half* __restrict__ A, int lda, long long strA,
           const __half* __restrict__ Bt, int ldbt, long long strB,
           void* __restrict__ Cv, int ldc, long long strC,
           const float* __restrict__ bias,
           const float* __restrict__ resid,
           float alpha, int K)
{
    extern __shared__ __half smh[];
    __half* As = smh;                  // NSTG x HTSZ
    __half* Bs = smh + NSTG*HTSZ;      // NSTG x HTSZ

    const __half* Ab = A  + (size_t)blockIdx.z * strA;
    const __half* Bg = Bt + (size_t)blockIdx.z * strB;

    const int m0 = blockIdx.y * 128, n0 = blockIdx.x * 128;
    const int tid = threadIdx.x, lane = tid & 31, wid = tid >> 5;
    const int wm = (wid >> 1) * 32;
    const int wn = (wid & 1)  * 64;

    const int trow = tid >> 1, tch = (tid & 1) * 2;

    const __half* agp = Ab + (size_t)(m0 + trow) * lda  + tch*8;
    const __half* bgp = Bg + (size_t)(n0 + trow) * ldbt + tch*8;

    unsigned asp[2], bsp[2];
    #pragma unroll
    for (int c = 0; c < 2; c++) {
        asp[c] = (unsigned)__cvta_generic_to_shared(&As[trow*HST + (tch+c)*8]);
        bsp[c] = (unsigned)__cvta_generic_to_shared(&Bs[trow*HST + (tch+c)*8]);
    }
    const unsigned BUFB = HTSZ * 2;    // bytes per buffer

    float acc[2][8][4];
    #pragma unroll
    for (int i = 0; i < 2; i++)
        #pragma unroll
        for (int j = 0; j < 8; j++)
            #pragma unroll
            for (int q = 0; q < 4; q++) acc[i][j][q] = 0.f;

    const int f_r  = (lane & 7) + ((lane >> 3) & 1) * 8;
    const int f_kh = ((lane >> 4) & 1) * 8;

    const int KIT = K / 32;

    // prologue: chunks 0 and 1 in flight (KIT >= 16 for all our shapes)
    #pragma unroll
    for (int c = 0; c < 2; c++) {
        asm volatile("cp.async.cg.shared.global [%0], [%1], 16;\n"
                     :: "r"(asp[c]), "l"(agp + c*8) : "memory");
        asm volatile("cp.async.cg.shared.global [%0], [%1], 16;\n"
                     :: "r"(bsp[c]), "l"(bgp + c*8) : "memory");
    }
    asm volatile("cp.async.commit_group;\n" ::: "memory");
    {
        const __half* ag = agp + 32;
        const __half* bg = bgp + 32;
        #pragma unroll
        for (int c = 0; c < 2; c++) {
            asm volatile("cp.async.cg.shared.global [%0], [%1], 16;\n"
                         :: "r"(asp[c] + BUFB), "l"(ag + c*8) : "memory");
            asm volatile("cp.async.cg.shared.global [%0], [%1], 16;\n"
                         :: "r"(bsp[c] + BUFB), "l"(bg + c*8) : "memory");
        }
    }
    asm volatile("cp.async.commit_group;\n" ::: "memory");

    int buf = 0;        // buffer holding chunk `it`
    int nbuf = 2;       // buffer for chunk `it+2`
    for (int it = 0; it < KIT; ++it) {
        asm volatile("cp.async.wait_group 1;\n" ::: "memory");
        __syncthreads();

        if (it + 2 < KIT) {
            const __half* ag = agp + (size_t)(it+2)*32;
            const __half* bg = bgp + (size_t)(it+2)*32;
            unsigned ob = (unsigned)nbuf * BUFB;
            #pragma unroll
            for (int c = 0; c < 2; c++) {
                asm volatile("cp.async.cg.shared.global [%0], [%1], 16;\n"
                             :: "r"(asp[c] + ob), "l"(ag + c*8) : "memory");
                asm volatile("cp.async.cg.shared.global [%0], [%1], 16;\n"
                             :: "r"(bsp[c] + ob), "l"(bg + c*8) : "memory");
            }
        }
        asm volatile("cp.async.commit_group;\n" ::: "memory");

        const __half* Abuf = As + buf*HTSZ;
        const __half* Bbuf = Bs + buf*HTSZ;

        #pragma unroll
        for (int ks = 0; ks < 2; ks++) {
            unsigned a[2][4];
            #pragma unroll
            for (int mt = 0; mt < 2; mt++) {
                unsigned addr = (unsigned)__cvta_generic_to_shared(
                    Abuf + (wm + mt*16 + f_r)*HST + ks*16 + f_kh);
                asm volatile("ldmatrix.sync.aligned.m8n8.x4.shared.b16 {%0,%1,%2,%3}, [%4];"
                    : "=r"(a[mt][0]), "=r"(a[mt][1]), "=r"(a[mt][2]), "=r"(a[mt][3])
                    : "r"(addr));
            }
            unsigned bf[4][4];
            #pragma unroll
            for (int p = 0; p < 4; p++) {
                unsigned addr = (unsigned)__cvta_generic_to_shared(
                    Bbuf + (wn + p*16 + f_r)*HST + ks*16 + f_kh);
                asm volatile("ldmatrix.sync.aligned.m8n8.x4.shared.b16 {%0,%1,%2,%3}, [%4];"
                    : "=r"(bf[p][0]), "=r"(bf[p][1]), "=r"(bf[p][2]), "=r"(bf[p][3])
                    : "r"(addr));
            }
            #pragma unroll
            for (int nt = 0; nt < 8; nt++) {
                unsigned b0 = bf[nt >> 1][(nt & 1)];
                unsigned b1 = bf[nt >> 1][(nt & 1) + 2];
                #pragma unroll
                for (int mt = 0; mt < 2; mt++) {
                    asm volatile(
                        "mma.sync.aligned.m16n8k16.row.col.f32.f16.f16.f32 "
                        "{%0,%1,%2,%3}, {%4,%5,%6,%7}, {%8,%9}, {%0,%1,%2,%3};"
                        : "+f"(acc[mt][nt][0]), "+f"(acc[mt][nt][1]),
                          "+f"(acc[mt][nt][2]), "+f"(acc[mt][nt][3])
                        : "r"(a[mt][0]), "r"(a[mt][1]), "r"(a[mt][2]), "r"(a[mt][3]),
                          "r"(b0), "r"(b1));
                }
            }
        }
        buf  = (buf  == 2) ? 0 : buf  + 1;
        nbuf = (nbuf == 2) ? 0 : nbuf + 1;
    }

    const int c_r = lane >> 2, c_c = (lane & 3) * 2;
    #pragma unroll
    for (int mt = 0; mt < 2; mt++) {
        #pragma unroll
        for (int nt = 0; nt < 8; nt++) {
            int row0 = m0 + wm + mt*16 + c_r;
            int col  = n0 + wn + nt*8 + c_c;
            float o0 = acc[mt][nt][0]*alpha, o1 = acc[mt][nt][1]*alpha;
            float o2 = acc[mt][nt][2]*alpha, o3 = acc[mt][nt][3]*alpha;
            if (bias) {
                float bx = bias[col], by = bias[col+1];
                o0 += bx; o1 += by; o2 += bx; o3 += by;
            }
            if (HOUT) {
                __half* Cb = (__half*)Cv + (size_t)blockIdx.z * strC;
                *(__half2*)(Cb + (size_t)row0*ldc + col)     = __floats2half2_rn(o0, o1);
                *(__half2*)(Cb + (size_t)(row0+8)*ldc + col) = __floats2half2_rn(o2, o3);
            } else {
                float* Cb = (float*)Cv + (size_t)blockIdx.z * strC;
                if (resid) {
                    float2 r0 = *(const float2*)(resid + (size_t)row0*ldc + col);
                    float2 r1 = *(const float2*)(resid + (size_t)(row0+8)*ldc + col);
                    o0 += r0.x; o1 += r0.y; o2 += r1.x; o3 += r1.y;
                }
                *(float2*)(Cb + (size_t)row0*ldc + col)     = make_float2(o0, o1);
                *(float2*)(Cb + (size_t)(row0+8)*ldc + col) = make_float2(o2, o3);
            }
        }
    }
}

// ---------------- row softmax: fp16 in -> fp16 out, half2 math + f16x2 MUFU ----------------
__global__ void softmax_kernel(const __half* __restrict__ s, __half* __restrict__ pout) {
    const __half2* p = reinterpret_cast<const __half2*>(s) + (size_t)blockIdx.x * (NTOK/2);
    __half2* po = reinterpret_cast<__half2*>(pout) + (size_t)blockIdx.x * (NTOK/2);
    const int tid = threadIdx.x, lane = tid & 31, wid = tid >> 5;

    __half2 v[8];
    #pragma unroll
    for (int t = 0; t < 8; t++) v[t] = p[tid + t*256];

    __half2 m2 = v[0];
    #pragma unroll
    for (int t = 1; t < 8; t++) m2 = __hmax2(m2, v[t]);
    #pragma unroll
    for (int o = 16; o > 0; o >>= 1) {
        unsigned mu = *(unsigned*)&m2;
        unsigned ou = __shfl_xor_sync(0xffffffffu, mu, o);
        m2 = __hmax2(m2, *(__half2*)&ou);
    }
    __shared__ __half2 mred[8];
    __shared__ float   sred[8];
    if (lane == 0) mred[wid] = m2;
    __syncthreads();
    m2 = mred[0];
    #pragma unroll
    for (int w = 1; w < 8; w++) m2 = __hmax2(m2, mred[w]);
    __half mm = __hmax(__low2half(m2), __high2half(m2));
    m2 = __half2half2(mm);

    const __half2 l2e = __float2half2_rn(1.44269504f);
    float sum = 0.f;
    #pragma unroll
    for (int t = 0; t < 8; t++) {
        __half2 xl = __hmul2(__hsub2(v[t], m2), l2e);
        unsigned xu = *(unsigned*)&xl, eu;
        asm("ex2.approx.f16x2 %0, %1;" : "=r"(eu) : "r"(xu));
        v[t] = *(__half2*)&eu;
        float2 f = __half22float2(v[t]);
        sum += f.x + f.y;
    }

    #pragma unroll
    for (int o = 16; o > 0; o >>= 1)
        sum += __shfl_xor_sync(0xffffffffu, sum, o);
    if (lane == 0) sred[wid] = sum;
    __syncthreads();
    float tot = 0.f;
    #pragma unroll
    for (int w = 0; w < 8; w++) tot += sred[w];
    __half2 r2 = __float2half2_rn(1.f / tot);

    #pragma unroll
    for (int t = 0; t < 8; t++)
        po[tid + t*256] = __hmul2(v[t], r2);
}

// ---------------- launch ----------------
extern "C" void kernel_launch(void* const* d_in, const int* in_sizes, int n_in,
                              void* d_out, int out_size) {
    const float* x  = (const float*)d_in[0];
    const float* gs = (const float*)d_in[1];
    const float* gb = (const float*)d_in[2];
    const float* wq = (const float*)d_in[3];
    const float* bq = (const float*)d_in[4];
    const float* wk = (const float*)d_in[5];
    const float* bk = (const float*)d_in[6];
    const float* wv = (const float*)d_in[7];
    const float* bv = (const float*)d_in[8];
    const float* wo = (const float*)d_in[9];
    const float* bo = (const float*)d_in[10];
    float* out = (float*)d_out;

    __half *h, *qkv, *vth, *ao, *sh, *pp, *w16;
    float *bqkv;
    cudaGetSymbolAddress((void**)&h,    g_h);
    cudaGetSymbolAddress((void**)&qkv,  g_qkv);
    cudaGetSymbolAddress((void**)&vth,  g_vth);
    cudaGetSymbolAddress((void**)&ao,   g_ao);
    cudaGetSymbolAddress((void**)&sh,   g_s);
    cudaGetSymbolAddress((void**)&pp,   g_p);
    cudaGetSymbolAddress((void**)&w16,  g_w16);
    cudaGetSymbolAddress((void**)&bqkv, g_bqkv);

    __half* wqkvT = w16;                            // [3*CC][CC]
    __half* woT   = w16 + 3*(size_t)CC*CC;          // [CC][CC]

    cudaFuncSetAttribute(hgemm<true>,  cudaFuncAttributeMaxDynamicSharedMemorySize, HSMEM);
    cudaFuncSetAttribute(hgemm<false>, cudaFuncAttributeMaxDynamicSharedMemorySize, HSMEM);

    const long long sNC  = (long long)NTOK * CC;
    const long long sNN  = (long long)NTOK * NTOK;
    const long long sQKV = (long long)NTOK * 3*CC;
    const int Mtot = Bb * NTOK;                      // 32768
    const float inv_sqrt_c = 0.044194173824159216f;  // 512^-0.5

    dim3 tb(32, 8);

    // 0) weight transposes -> fp16 (wq/wk/wv into packed sections), bias pack
    dim3 gtw(CC/32, CC/32, 1);
    transpose_f2h<<<gtw, tb>>>(wq, wqkvT,                       CC, CC);
    transpose_f2h<<<gtw, tb>>>(wk, wqkvT +   (size_t)CC*CC,     CC, CC);
    transpose_f2h<<<gtw, tb>>>(wv, wqkvT + 2*(size_t)CC*CC,     CC, CC);
    transpose_f2h<<<gtw, tb>>>(wo, woT,                         CC, CC);
    pack_bias<<<6, 256>>>(bq, bk, bv, bqkv);

    // 1) GroupNorm -> fp16 h
    gn_kernel<<<Bb*GG, 256>>>(x, gs, gb, h);

    // 2) fused QKV projection: [32768,512] @ [512,1536] -> packed qkv fp16
    dim3 gqkv(3*CC/128, Mtot/128, 1);
    hgemm<true><<<gqkv, 256, HSMEM>>>(h, CC, 0, wqkvT, CC, 0, qkv, 3*CC, 0,
                                      bqkv, nullptr, 1.f, CC);

    // 3) V -> V^T fp16 per batch (v = qkv section 2, ldi = 1536)
    dim3 gtv(NTOK/32, CC/32, Bb);
    transpose_h2h<<<gtv, tb>>>(qkv + 2*CC, vth, NTOK, CC, 3*CC, sQKV, sNC);

    // 4) scores = alpha * Q @ K^T (fp16 in, fp16 out; alpha in epilogue)
    dim3 gsc(NTOK/128, NTOK/128, Bb);
    hgemm<true><<<gsc, 256, HSMEM>>>(qkv, 3*CC, sQKV, qkv + CC, 3*CC, sQKV,
                                     sh, NTOK, sNN, nullptr, nullptr, inv_sqrt_c, CC);

    // 5) softmax: fp16 scores -> fp16 P (half2 + f16x2 MUFU)
    softmax_kernel<<<Bb*NTOK, 256>>>(sh, pp);

    // 6) attn @ V fp16 -> ao fp16
    dim3 gav(CC/128, NTOK/128, Bb);
    hgemm<true><<<gav, 256, HSMEM>>>(pp, NTOK, sNN, vth, NTOK, sNC,
                                     ao, CC, sNC, nullptr, nullptr, 1.f, NTOK);

    // 7) output projection + bias + residual -> d_out (fp32)
    dim3 gout(CC/128, Mtot/128, 1);
    hgemm<false><<<gout, 256, HSMEM>>>(ao, CC, 0, woT, CC, 0, out, CC, 0,
                                       bo, x, 1.f, CC);
}